// round 10
// baseline (speedup 1.0000x reference)
#include <cuda_runtime.h>
#include <cstdint>

#define FILL_I (-1000000)

#define NPAD_H 18
#define NPAD_M 68

__device__ float g_tmpA[(3 * 2160 + NPAD_H) * 256];
__device__ float g_tmpB[(3 * 2160 + NPAD_M) * 64];
__device__ float g_hx[3 * 256 * 256];
__device__ float g_mx[3 * 64 * 64];
__device__ unsigned g_bits[256 * 8];
__device__ int   g_coords[256 * 2];

#define OFF_COORDS 65536
#define OFF_SURV   66048
#define OFF_LOGITS 66304
#define OFF_LABELS 68096

// compile-time normalized triangle weights (interior outputs, horizontal)
__device__ __forceinline__ constexpr float WAc(int k) {
    return (float)((15.0 - ((k < 15) ? (15 - k) : (k - 15))) / 225.0);
}
__device__ __forceinline__ constexpr float WBc(int k) {
    double d = (k < 60) ? (59.5 - k) : (k - 59.5);
    return (float)((60.0 - d) / 3600.0);
}

// ---------------- K1: horizontal pass --------------------------------------
__global__ __launch_bounds__(256) void k_hresize(const float* __restrict__ x) {
    __shared__ float row[2][4032];
    __shared__ float pb[4][2][64];
    int b = blockIdx.x;                 // 3240 = 3ch * 1080 row pairs
    int c = b / 1080;
    int iy = (b - c * 1080) * 2;
    const float4* src4 = (const float4*)(x + ((size_t)(c * 2160 + iy)) * 3840);
    for (int idx = threadIdx.x; idx < 2016; idx += 256) {
        int rr = idx < 1008 ? 0 : 1;
        int j = idx < 1008 ? idx : idx - 1008;
        float4 v = make_float4(0.f, 0.f, 0.f, 0.f);
        if (j >= 8 && j < 968) v = src4[rr * 960 + (j - 8)];
        *(float4*)(&row[rr][j * 4]) = v;
    }
    __syncthreads();
    int t = threadIdx.x;
    size_t rbase = (size_t)(c * 2160 + iy);

    // A side
    {
        int sb = 15 * t + 24;
        float a0 = 0.f, a1 = 0.f;
        #pragma unroll
        for (int k = 1; k <= 29; k++) {
            a0 = fmaf(WAc(k), row[0][sb + k], a0);
            a1 = fmaf(WAc(k), row[1][sb + k], a1);
        }
        if (t == 0 || t == 255) { a0 *= (225.f / 197.f); a1 *= (225.f / 197.f); }
        g_tmpA[rbase * 256 + t]       = a0;
        g_tmpA[(rbase + 1) * 256 + t] = a1;
    }

    // B side
    {
        int o = t & 63, q = t >> 6;
        int sb = 60 * o + 2;
        float b0 = 0.f, b1 = 0.f;
        #define BQ(K0)                                                    \
            _Pragma("unroll")                                             \
            for (int j = 0; j < 30; j++) {                                \
                b0 = fmaf(WBc((K0) + j), row[0][sb + (K0) + j], b0);      \
                b1 = fmaf(WBc((K0) + j), row[1][sb + (K0) + j], b1);      \
            }
        if      (q == 0) { BQ(0)  }
        else if (q == 1) { BQ(30) }
        else if (q == 2) { BQ(60) }
        else             { BQ(90) }
        #undef BQ
        pb[q][0][o] = b0;
        pb[q][1][o] = b1;
    }
    __syncthreads();
    if (t < 64) {
        float s0 = pb[0][0][t] + pb[1][0][t] + pb[2][0][t] + pb[3][0][t];
        float s1 = pb[0][1][t] + pb[1][1][t] + pb[2][1][t] + pb[3][1][t];
        if (t == 0 || t == 63) { s0 *= (8.f / 7.f); s1 *= (8.f / 7.f); }
        g_tmpB[rbase * 64 + t]       = s0;
        g_tmpB[(rbase + 1) * 64 + t] = s1;
    }
}

// ---------------- K2: vertical passes, smem weights + float4 loads ----------
__global__ __launch_bounds__(256) void k_vresize() {
    int b = blockIdx.x;
    int tid = threadIdx.x;
    if (b < 192) {
        __shared__ float sw[4][NPAD_H];
        __shared__ float sws[4];
        __shared__ int   ssi[4];
        if (tid < 4 * NPAD_H) {
            int rowi = tid / NPAD_H, k = tid % NPAD_H;
            int oy = (b * 4 + rowi) & 255;
            float sample = fmaf((float)oy + 0.5f, 8.4375f, -0.5f);
            int s = (int)ceilf(sample - 8.4375f); if (s < 0) s = 0;
            int pos = s + k;
            float d = fabsf(sample - (float)pos) * (1.0f / 8.4375f);
            float w = fmaxf(1.0f - d, 0.f);
            if (pos > 2159) w = 0.f;
            sw[rowi][k] = w;
            if (k == 0) ssi[rowi] = s;
        }
        __syncthreads();
        if (tid < 4) {
            float s = 0.f;
            #pragma unroll
            for (int k = 0; k < NPAD_H; k++) s += sw[tid][k];
            sws[tid] = 1.0f / s;
        }
        __syncthreads();
        int rowi = tid >> 6, c4 = tid & 63;
        int lin = b * 4 + rowi;
        int ch = lin >> 8, oy = lin & 255;
        int s = ssi[rowi];
        float4 acc = make_float4(0.f, 0.f, 0.f, 0.f);
        #pragma unroll
        for (int k = 0; k < NPAD_H; k++) {
            float w = sw[rowi][k];
            float4 v = *(const float4*)(g_tmpA + ((size_t)(ch * 2160 + s + k)) * 256 + c4 * 4);
            acc.x = fmaf(w, v.x, acc.x);
            acc.y = fmaf(w, v.y, acc.y);
            acc.z = fmaf(w, v.z, acc.z);
            acc.w = fmaf(w, v.w, acc.w);
        }
        float inv = sws[rowi];
        float4 o = make_float4(acc.x * inv, acc.y * inv, acc.z * inv, acc.w * inv);
        *(float4*)(g_hx + (ch * 256 + oy) * 256 + c4 * 4) = o;
    } else {
        __shared__ float sw[16][NPAD_M];
        __shared__ float sws[16];
        __shared__ int   ssi[16];
        int bb = b - 192;
        for (int i = tid; i < 16 * NPAD_M; i += 256) {
            int rowi = i / NPAD_M, k = i % NPAD_M;
            int oy = (bb * 16 + rowi) & 63;
            float sample = fmaf((float)oy + 0.5f, 33.75f, -0.5f);
            int s = (int)ceilf(sample - 33.75f); if (s < 0) s = 0;
            int pos = s + k;
            float d = fabsf(sample - (float)pos) * (1.0f / 33.75f);
            float w = fmaxf(1.0f - d, 0.f);
            if (pos > 2159) w = 0.f;
            sw[rowi][k] = w;
            if (k == 0) ssi[rowi] = s;
        }
        __syncthreads();
        if (tid < 16) {
            float s = 0.f;
            for (int k = 0; k < NPAD_M; k++) s += sw[tid][k];
            sws[tid] = 1.0f / s;
        }
        __syncthreads();
        int rowi = tid >> 4, c4 = tid & 15;
        int row = bb * 16 + rowi;
        int ch = row >> 6, oy = row & 63;
        int s = ssi[rowi];
        float4 acc = make_float4(0.f, 0.f, 0.f, 0.f);
        #pragma unroll 4
        for (int k = 0; k < NPAD_M; k++) {
            float w = sw[rowi][k];
            float4 v = *(const float4*)(g_tmpB + ((size_t)(ch * 2160 + s + k)) * 64 + c4 * 4);
            acc.x = fmaf(w, v.x, acc.x);
            acc.y = fmaf(w, v.y, acc.y);
            acc.z = fmaf(w, v.z, acc.z);
            acc.w = fmaf(w, v.w, acc.w);
        }
        float inv = sws[rowi];
        float4 o = make_float4(acc.x * inv, acc.y * inv, acc.z * inv, acc.w * inv);
        *(float4*)(g_mx + (ch * 64 + oy) * 64 + c4 * 4) = o;
    }
}

// ---------------- K3: heat conv + mask + peak, 1 row per block --------------
__global__ __launch_bounds__(256) void k_heatpeak(const float* __restrict__ lw, const float* __restrict__ lb,
                                                  const float* __restrict__ mw, const float* __restrict__ mb,
                                                  float* __restrict__ out) {
    __shared__ float sx[3][5][256];
    __shared__ float smx[3][4][66];
    __shared__ float sh[3][258];
    int tid = threadIdx.x;
    int r = blockIdx.x;
    int base = (r - 1) >> 2;

    for (int idx = tid; idx < 960; idx += 256) {
        int c4 = idx & 63;
        int i = (idx >> 6) % 5;
        int ch = idx / 320;
        int gr = r - 2 + i;
        float4 v = make_float4(0.f, 0.f, 0.f, 0.f);
        if (gr >= 0 && gr < 256)
            v = *(const float4*)(g_hx + (ch << 16) + gr * 256 + c4 * 4);
        *(float4*)(&sx[ch][i][c4 * 4]) = v;
    }
    if (tid < 192) {
        int c4 = tid & 15;
        int i = (tid >> 4) & 3;
        int ch = tid >> 6;
        int gr = base - 1 + i;
        float4 v = make_float4(0.f, 0.f, 0.f, 0.f);
        if (gr >= 0 && gr < 64)
            v = *(const float4*)(g_mx + (ch * 64 + gr) * 64 + c4 * 4);
        smx[ch][i][c4 * 4 + 1] = v.x;
        smx[ch][i][c4 * 4 + 2] = v.y;
        smx[ch][i][c4 * 4 + 3] = v.z;
        smx[ch][i][c4 * 4 + 4] = v.w;
    }
    if (tid < 24) { int ch = tid / 8, i = (tid >> 1) & 3, side = tid & 1; smx[ch][i][side ? 65 : 0] = 0.f; }
    if (tid < 6)  { int j = tid >> 1, side = tid & 1; sh[j][side ? 257 : 0] = 0.f; }

    float w[27];
    #pragma unroll
    for (int k = 0; k < 27; k++) w[k] = __ldg(lw + k);
    float bias = __ldg(lb);
    float mbias = __ldg(mb);
    float mwr[27];
    #pragma unroll
    for (int k = 0; k < 27; k++) mwr[k] = __ldg(mw + k);
    __syncthreads();

    __shared__ float sm[2][64];
    if (tid < 128) {
        int li = 1 + (tid >> 6);
        int mcol = tid & 63;
        float macc = mbias;
        #pragma unroll
        for (int ic = 0; ic < 3; ic++)
            #pragma unroll
            for (int kr = 0; kr < 3; kr++)
                #pragma unroll
                for (int kc = 0; kc < 3; kc++)
                    macc = fmaf(smx[ic][li + kr - 1][mcol + kc], mwr[ic * 9 + kr * 3 + kc], macc);
        float v = fminf(fmaxf(macc, 0.f), 1.f);
        if (v < 0.6f) v = 0.f;
        sm[tid >> 6][mcol] = v;
    }
    __syncthreads();

    int c = tid;
    float acc[3] = {bias, bias, bias};
    #pragma unroll
    for (int ch = 0; ch < 3; ch++) {
        #pragma unroll
        for (int i = 0; i < 5; i++) {
            float vm = (c > 0)   ? sx[ch][i][c - 1] : 0.f;
            float v0 = sx[ch][i][c];
            float vp = (c < 255) ? sx[ch][i][c + 1] : 0.f;
            #pragma unroll
            for (int j = 0; j < 3; j++) {
                int kr = i - j;
                if (kr >= 0 && kr <= 2) {
                    acc[j] = fmaf(w[ch * 9 + kr * 3 + 0], vm,
                             fmaf(w[ch * 9 + kr * 3 + 1], v0,
                             fmaf(w[ch * 9 + kr * 3 + 2], vp, acc[j])));
                }
            }
        }
    }
    #pragma unroll
    for (int j = 0; j < 3; j++) {
        int rj = r - 1 + j;
        float heat = 0.f;
        if (rj >= 0 && rj < 256) {
            float hm = fminf(fmaxf(acc[j], 0.f), 1.f);
            if (hm < 0.4f) hm = 0.f;
            heat = hm * sm[(rj >> 2) - base][c >> 2];
        }
        sh[j][c + 1] = heat;
    }
    __syncthreads();

    float v = sh[1][c + 1];
    bool pk = (v > sh[1][c]) && (v > sh[1][c + 2]) &&
              (v > sh[0][c + 1]) && (v > sh[2][c + 1]);
    unsigned m = __ballot_sync(0xffffffffu, pk);
    if ((c & 31) == 0) g_bits[r * 8 + (c >> 5)] = m;
    out[r * 256 + c] = v;
}

// ---------------- K4: ordered compaction (warp-shuffle scan) ----------------
__global__ __launch_bounds__(256) void k_compact() {
    __shared__ int wsum[8];
    int t = threadIdx.x;
    int lane = t & 31, wid = t >> 5;
    unsigned b[8]; int cnt = 0;
    #pragma unroll
    for (int w = 0; w < 8; w++) { b[w] = g_bits[t * 8 + w]; cnt += __popc(b[w]); }
    int scan = cnt;
    #pragma unroll
    for (int off = 1; off < 32; off <<= 1) {
        int v = __shfl_up_sync(0xffffffffu, scan, off);
        if (lane >= off) scan += v;
    }
    if (lane == 31) wsum[wid] = scan;
    __syncthreads();
    int wbase = 0, total = 0;
    #pragma unroll
    for (int wi = 0; wi < 8; wi++) {
        int s = wsum[wi];
        wbase += (wi < wid) ? s : 0;
        total += s;
    }
    int pos = wbase + scan - cnt;
    #pragma unroll
    for (int w = 0; w < 8; w++) {
        unsigned bits = b[w];
        while (bits) {
            int j = __ffs(bits) - 1; bits &= bits - 1;
            if (pos < 256) { g_coords[2 * pos] = t; g_coords[2 * pos + 1] = w * 32 + j; }
            pos++;
        }
    }
    if (t >= total) { g_coords[2 * t] = FILL_I; g_coords[2 * t + 1] = FILL_I; }
}

// ---------------- K5: survive (distributed) + classify ----------------------
__global__ __launch_bounds__(256) void k_classify(const float* __restrict__ W, const float* __restrict__ bias,
                                                  float* __restrict__ out) {
    int bx = blockIdx.x;
    int t = threadIdx.x;
    int rme = g_coords[2 * bx], cme = g_coords[2 * bx + 1];
    int rt  = g_coords[2 * t],  ct  = g_coords[2 * t + 1];
    float dx = (float)rt - (float)rme, dy = (float)ct - (float)cme;
    float d2 = dx * dx + dy * dy;
    int vit = (rt > FILL_I);
    int rej = __syncthreads_or(vit && (d2 > 1.0f) && (d2 < 9.0f));
    int sv = (rme > FILL_I) && !rej;
    if (t == 0) {
        out[OFF_COORDS + 2 * bx]     = (float)rme;
        out[OFF_COORDS + 2 * bx + 1] = (float)cme;
        out[OFF_SURV + bx]           = (float)sv;
    }
    if (!sv) {
        if (t < 7) out[OFF_LOGITS + bx * 7 + t] = 0.f;
        if (t == 0) out[OFF_LABELS + bx] = 0.f;
        return;
    }
    int r0 = min(max(rme, 0), 255);
    int c0 = min(max(cme, 0), 255);
    float part[7] = {0.f, 0.f, 0.f, 0.f, 0.f, 0.f, 0.f};
    #pragma unroll
    for (int it = 0; it < 12; it++) {
        int f = t + it * 256;
        int ch = f >> 10, rem = f & 1023, wr = rem >> 5, wc = rem & 31;
        int rr = r0 + wr - 16, cc = c0 + wc - 16;
        float v = 0.f;
        if (rr >= 0 && rr < 256 && cc >= 0 && cc < 256)
            v = g_hx[(ch << 16) + rr * 256 + cc];
        const float* wrow = W + f * 7;
        #pragma unroll
        for (int k = 0; k < 7; k++) part[k] = fmaf(v, wrow[k], part[k]);
    }
    #pragma unroll
    for (int off = 16; off > 0; off >>= 1)
        #pragma unroll
        for (int k = 0; k < 7; k++)
            part[k] += __shfl_down_sync(0xffffffffu, part[k], off);
    __shared__ float sw[8][7];
    if ((t & 31) == 0)
        #pragma unroll
        for (int k = 0; k < 7; k++) sw[t >> 5][k] = part[k];
    __syncthreads();
    if (t == 0) {
        float l[7], e[7];
        float m = -1e30f;
        #pragma unroll
        for (int k = 0; k < 7; k++) {
            float s = bias[k];
            #pragma unroll
            for (int wi = 0; wi < 8; wi++) s += sw[wi][k];
            l[k] = s; m = fmaxf(m, s);
        }
        float s = 0.f;
        #pragma unroll
        for (int k = 0; k < 7; k++) { e[k] = expf(l[k] - m); s += e[k]; }
        float inv = 1.0f / s;
        int best = 0; float bv = -1e30f;
        #pragma unroll
        for (int k = 0; k < 7; k++) {
            float smv = e[k] * inv;
            out[OFF_LOGITS + bx * 7 + k] = smv;
            if (smv > bv) { bv = smv; best = k; }
        }
        out[OFF_LABELS + bx] = (float)best;
    }
}

// ---------------- launch ------------------------------------------------------
extern "C" void kernel_launch(void* const* d_in, const int* in_sizes, int n_in,
                              void* d_out, int out_size) {
    const float* x    = (const float*)d_in[0];
    const float* locw = (const float*)d_in[1];
    const float* locb = (const float*)d_in[2];
    const float* mskw = (const float*)d_in[3];
    const float* mskb = (const float*)d_in[4];
    const float* lblw = (const float*)d_in[5];
    const float* lblb = (const float*)d_in[6];
    float* out = (float*)d_out;

    k_hresize<<<3240, 256>>>(x);
    k_vresize<<<204, 256>>>();
    k_heatpeak<<<256, 256>>>(locw, locb, mskw, mskb, out);
    k_compact<<<1, 256>>>();
    k_classify<<<256, 256>>>(lblw, lblb, out);
}

// round 11
// speedup vs baseline: 1.2159x; 1.2159x over previous
#include <cuda_runtime.h>
#include <cstdint>

#define FILL_I (-1000000)

#define NPAD_H 18
#define NPAD_M 68

__device__ float g_tmpA[(3 * 2160 + NPAD_H) * 256];
__device__ float g_tmpB[(3 * 2160 + NPAD_M) * 64];
__device__ float g_hx[3 * 256 * 256];
__device__ float g_mx[3 * 64 * 64];
__device__ unsigned g_bits[256 * 8];

#define OFF_COORDS 65536
#define OFF_SURV   66048
#define OFF_LOGITS 66304
#define OFF_LABELS 68096

// compile-time normalized triangle weights (interior outputs, horizontal)
__device__ __forceinline__ constexpr float WAc(int k) {
    return (float)((15.0 - ((k < 15) ? (15 - k) : (k - 15))) / 225.0);
}
__device__ __forceinline__ constexpr float WBc(int k) {
    double d = (k < 60) ? (59.5 - k) : (k - 59.5);
    return (float)((60.0 - d) / 3600.0);
}

// ---------------- K1: horizontal pass (R8 form) ------------------------------
__global__ __launch_bounds__(256) void k_hresize(const float* __restrict__ x) {
    __shared__ float row[2][4032];
    __shared__ float pb[4][2][64];
    int b = blockIdx.x;                 // 3240 = 3ch * 1080 row pairs
    int c = b / 1080;
    int iy = (b - c * 1080) * 2;
    const float4* src4 = (const float4*)(x + ((size_t)(c * 2160 + iy)) * 3840);
    for (int idx = threadIdx.x; idx < 2016; idx += 256) {
        int rr = idx < 1008 ? 0 : 1;
        int j = idx < 1008 ? idx : idx - 1008;
        float4 v = make_float4(0.f, 0.f, 0.f, 0.f);
        if (j >= 8 && j < 968) v = src4[rr * 960 + (j - 8)];
        *(float4*)(&row[rr][j * 4]) = v;
    }
    __syncthreads();
    int t = threadIdx.x;
    size_t rbase = (size_t)(c * 2160 + iy);

    // A side
    {
        int sb = 15 * t + 24;
        float a0 = 0.f, a1 = 0.f;
        #pragma unroll
        for (int k = 1; k <= 29; k++) {
            a0 = fmaf(WAc(k), row[0][sb + k], a0);
            a1 = fmaf(WAc(k), row[1][sb + k], a1);
        }
        if (t == 0 || t == 255) { a0 *= (225.f / 197.f); a1 *= (225.f / 197.f); }
        g_tmpA[rbase * 256 + t]       = a0;
        g_tmpA[(rbase + 1) * 256 + t] = a1;
    }

    // B side
    {
        int o = t & 63, q = t >> 6;
        int sb = 60 * o + 2;
        float b0 = 0.f, b1 = 0.f;
        #define BQ(K0)                                                    \
            _Pragma("unroll")                                             \
            for (int j = 0; j < 30; j++) {                                \
                b0 = fmaf(WBc((K0) + j), row[0][sb + (K0) + j], b0);      \
                b1 = fmaf(WBc((K0) + j), row[1][sb + (K0) + j], b1);      \
            }
        if      (q == 0) { BQ(0)  }
        else if (q == 1) { BQ(30) }
        else if (q == 2) { BQ(60) }
        else             { BQ(90) }
        #undef BQ
        pb[q][0][o] = b0;
        pb[q][1][o] = b1;
    }
    __syncthreads();
    if (t < 64) {
        float s0 = pb[0][0][t] + pb[1][0][t] + pb[2][0][t] + pb[3][0][t];
        float s1 = pb[0][1][t] + pb[1][1][t] + pb[2][1][t] + pb[3][1][t];
        if (t == 0 || t == 63) { s0 *= (8.f / 7.f); s1 *= (8.f / 7.f); }
        g_tmpB[rbase * 64 + t]       = s0;
        g_tmpB[(rbase + 1) * 64 + t] = s1;
    }
}

// ---------------- K2: fused vertical passes (R8 form, 816 blocks) -----------
__global__ __launch_bounds__(256) void k_vresize() {
    int b = blockIdx.x;
    int tid = threadIdx.x;
    if (b < 768) {
        int ch = b >> 8, oy = b & 255;
        float sample = fmaf((float)oy + 0.5f, 8.4375f, -0.5f);
        int s = (int)ceilf(sample - 8.4375f); if (s < 0) s = 0;
        float acc = 0.f, wsum = 0.f;
        #pragma unroll
        for (int k = 0; k < NPAD_H; k++) {
            int pos = s + k;
            float d = fabsf(sample - (float)pos) * (1.0f / 8.4375f);
            float w = fmaxf(1.0f - d, 0.f);
            if (pos > 2159) w = 0.f;
            wsum += w;
            acc = fmaf(w, g_tmpA[((size_t)(ch * 2160 + pos)) * 256 + tid], acc);
        }
        g_hx[(ch * 256 + oy) * 256 + tid] = acc / wsum;
    } else {
        int lin = (b - 768) * 4 + (tid >> 6);
        int ox = tid & 63;
        int ch = lin >> 6, oy = lin & 63;
        float sample = fmaf((float)oy + 0.5f, 33.75f, -0.5f);
        int s = (int)ceilf(sample - 33.75f); if (s < 0) s = 0;
        float acc = 0.f, wsum = 0.f;
        #pragma unroll
        for (int k = 0; k < NPAD_M; k++) {
            int pos = s + k;
            float d = fabsf(sample - (float)pos) * (1.0f / 33.75f);
            float w = fmaxf(1.0f - d, 0.f);
            if (pos > 2159) w = 0.f;
            wsum += w;
            acc = fmaf(w, g_tmpB[((size_t)(ch * 2160 + pos)) * 64 + ox], acc);
        }
        g_mx[(ch * 64 + oy) * 64 + ox] = acc / wsum;
    }
}

// ---------------- K3: heat conv + mask + peak (R8 form) ---------------------
__global__ __launch_bounds__(256) void k_heatpeak(const float* __restrict__ lw, const float* __restrict__ lb,
                                                  const float* __restrict__ mw, const float* __restrict__ mb,
                                                  float* __restrict__ out) {
    __shared__ float sx[3][5][256];
    __shared__ float smx[3][4][66];
    __shared__ float sh[3][258];
    int tid = threadIdx.x;
    int r = blockIdx.x;
    int base = (r - 1) >> 2;

    for (int idx = tid; idx < 960; idx += 256) {
        int c4 = idx & 63;
        int i = (idx >> 6) % 5;
        int ch = idx / 320;
        int gr = r - 2 + i;
        float4 v = make_float4(0.f, 0.f, 0.f, 0.f);
        if (gr >= 0 && gr < 256)
            v = *(const float4*)(g_hx + (ch << 16) + gr * 256 + c4 * 4);
        *(float4*)(&sx[ch][i][c4 * 4]) = v;
    }
    if (tid < 192) {
        int c4 = tid & 15;
        int i = (tid >> 4) & 3;
        int ch = tid >> 6;
        int gr = base - 1 + i;
        float4 v = make_float4(0.f, 0.f, 0.f, 0.f);
        if (gr >= 0 && gr < 64)
            v = *(const float4*)(g_mx + (ch * 64 + gr) * 64 + c4 * 4);
        smx[ch][i][c4 * 4 + 1] = v.x;
        smx[ch][i][c4 * 4 + 2] = v.y;
        smx[ch][i][c4 * 4 + 3] = v.z;
        smx[ch][i][c4 * 4 + 4] = v.w;
    }
    if (tid < 24) { int ch = tid / 8, i = (tid >> 1) & 3, side = tid & 1; smx[ch][i][side ? 65 : 0] = 0.f; }
    if (tid < 6)  { int j = tid >> 1, side = tid & 1; sh[j][side ? 257 : 0] = 0.f; }

    float w[27];
    #pragma unroll
    for (int k = 0; k < 27; k++) w[k] = __ldg(lw + k);
    float bias = __ldg(lb);
    float mbias = __ldg(mb);
    float mwr[27];
    #pragma unroll
    for (int k = 0; k < 27; k++) mwr[k] = __ldg(mw + k);
    __syncthreads();

    __shared__ float sm[2][64];
    if (tid < 128) {
        int li = 1 + (tid >> 6);
        int mcol = tid & 63;
        float macc = mbias;
        #pragma unroll
        for (int ic = 0; ic < 3; ic++)
            #pragma unroll
            for (int kr = 0; kr < 3; kr++)
                #pragma unroll
                for (int kc = 0; kc < 3; kc++)
                    macc = fmaf(smx[ic][li + kr - 1][mcol + kc], mwr[ic * 9 + kr * 3 + kc], macc);
        float v = fminf(fmaxf(macc, 0.f), 1.f);
        if (v < 0.6f) v = 0.f;
        sm[tid >> 6][mcol] = v;
    }
    __syncthreads();

    int c = tid;
    float acc[3] = {bias, bias, bias};
    #pragma unroll
    for (int ch = 0; ch < 3; ch++) {
        #pragma unroll
        for (int i = 0; i < 5; i++) {
            float vm = (c > 0)   ? sx[ch][i][c - 1] : 0.f;
            float v0 = sx[ch][i][c];
            float vp = (c < 255) ? sx[ch][i][c + 1] : 0.f;
            #pragma unroll
            for (int j = 0; j < 3; j++) {
                int kr = i - j;
                if (kr >= 0 && kr <= 2) {
                    acc[j] = fmaf(w[ch * 9 + kr * 3 + 0], vm,
                             fmaf(w[ch * 9 + kr * 3 + 1], v0,
                             fmaf(w[ch * 9 + kr * 3 + 2], vp, acc[j])));
                }
            }
        }
    }
    #pragma unroll
    for (int j = 0; j < 3; j++) {
        int rj = r - 1 + j;
        float heat = 0.f;
        if (rj >= 0 && rj < 256) {
            float hm = fminf(fmaxf(acc[j], 0.f), 1.f);
            if (hm < 0.4f) hm = 0.f;
            heat = hm * sm[(rj >> 2) - base][c >> 2];
        }
        sh[j][c + 1] = heat;
    }
    __syncthreads();

    float v = sh[1][c + 1];
    bool pk = (v > sh[1][c]) && (v > sh[1][c + 2]) &&
              (v > sh[0][c + 1]) && (v > sh[2][c + 1]);
    unsigned m = __ballot_sync(0xffffffffu, pk);
    if ((c & 31) == 0) g_bits[r * 8 + (c >> 5)] = m;
    out[r * 256 + c] = v;
}

// ---------------- K4: in-block compact + survive + classify ------------------
// Each block independently re-derives the ordered coords from g_bits via a
// cheap warp-shuffle scan (2 barriers), computes its candidate's survive via
// a block OR, then classifies. Block 0 writes coords + survive outputs.
__global__ __launch_bounds__(256) void k_classify(const float* __restrict__ W, const float* __restrict__ bias,
                                                  float* __restrict__ out) {
    __shared__ int wsum[8];
    __shared__ int sr[256], scc[256];
    int t = threadIdx.x, bx = blockIdx.x;
    int lane = t & 31, wid = t >> 5;

    // vectorized bitmask load: 8 words = 32B contiguous
    uint4 v0 = *(const uint4*)(g_bits + t * 8);
    uint4 v1 = *(const uint4*)(g_bits + t * 8 + 4);
    unsigned bb[8] = {v0.x, v0.y, v0.z, v0.w, v1.x, v1.y, v1.z, v1.w};
    int cnt = 0;
    #pragma unroll
    for (int w = 0; w < 8; w++) cnt += __popc(bb[w]);
    int scan = cnt;
    #pragma unroll
    for (int off = 1; off < 32; off <<= 1) {
        int vv = __shfl_up_sync(0xffffffffu, scan, off);
        if (lane >= off) scan += vv;
    }
    if (lane == 31) wsum[wid] = scan;
    __syncthreads();
    int wbase = 0, total = 0;
    #pragma unroll
    for (int wi = 0; wi < 8; wi++) {
        int s = wsum[wi];
        wbase += (wi < wid) ? s : 0;
        total += s;
    }
    int pos = wbase + scan - cnt;
    #pragma unroll
    for (int w = 0; w < 8; w++) {
        unsigned bits = bb[w];
        while (bits) {
            int j = __ffs(bits) - 1; bits &= bits - 1;
            if (pos < 256) { sr[pos] = t; scc[pos] = w * 32 + j; }
            pos++;
        }
    }
    if (t >= total) { sr[t] = FILL_I; scc[t] = FILL_I; }
    __syncthreads();

    int rme = sr[bx], cme = scc[bx];
    int rt = sr[t], ct = scc[t];
    float dx = (float)rt - (float)rme, dy = (float)ct - (float)cme;
    float d2 = dx * dx + dy * dy;
    int vit = (rt > FILL_I);
    int rej = __syncthreads_or(vit && (d2 > 1.0f) && (d2 < 9.0f));
    int sv = (rme > FILL_I) && !rej;

    if (bx == 0) {
        out[OFF_COORDS + 2 * t]     = (float)rt;
        out[OFF_COORDS + 2 * t + 1] = (float)ct;
    }
    if (t == 0) out[OFF_SURV + bx] = (float)sv;

    if (!sv) {
        if (t < 7) out[OFF_LOGITS + bx * 7 + t] = 0.f;
        if (t == 0) out[OFF_LABELS + bx] = 0.f;
        return;
    }
    int r0 = min(max(rme, 0), 255);
    int c0 = min(max(cme, 0), 255);
    float part[7] = {0.f, 0.f, 0.f, 0.f, 0.f, 0.f, 0.f};
    #pragma unroll
    for (int it = 0; it < 12; it++) {
        int f = t + it * 256;
        int ch = f >> 10, rem = f & 1023, wr = rem >> 5, wc = rem & 31;
        int rr = r0 + wr - 16, cc = c0 + wc - 16;
        float v = 0.f;
        if (rr >= 0 && rr < 256 && cc >= 0 && cc < 256)
            v = g_hx[(ch << 16) + rr * 256 + cc];
        const float* wrow = W + f * 7;
        #pragma unroll
        for (int k = 0; k < 7; k++) part[k] = fmaf(v, wrow[k], part[k]);
    }
    #pragma unroll
    for (int off = 16; off > 0; off >>= 1)
        #pragma unroll
        for (int k = 0; k < 7; k++)
            part[k] += __shfl_down_sync(0xffffffffu, part[k], off);
    __shared__ float sw[8][7];
    if ((t & 31) == 0)
        #pragma unroll
        for (int k = 0; k < 7; k++) sw[t >> 5][k] = part[k];
    __syncthreads();
    if (t == 0) {
        float l[7], e[7];
        float m = -1e30f;
        #pragma unroll
        for (int k = 0; k < 7; k++) {
            float s = bias[k];
            #pragma unroll
            for (int wi = 0; wi < 8; wi++) s += sw[wi][k];
            l[k] = s; m = fmaxf(m, s);
        }
        float s = 0.f;
        #pragma unroll
        for (int k = 0; k < 7; k++) { e[k] = expf(l[k] - m); s += e[k]; }
        float inv = 1.0f / s;
        int best = 0; float bv = -1e30f;
        #pragma unroll
        for (int k = 0; k < 7; k++) {
            float smv = e[k] * inv;
            out[OFF_LOGITS + bx * 7 + k] = smv;
            if (smv > bv) { bv = smv; best = k; }
        }
        out[OFF_LABELS + bx] = (float)best;
    }
}

// ---------------- launch ------------------------------------------------------
extern "C" void kernel_launch(void* const* d_in, const int* in_sizes, int n_in,
                              void* d_out, int out_size) {
    const float* x    = (const float*)d_in[0];
    const float* locw = (const float*)d_in[1];
    const float* locb = (const float*)d_in[2];
    const float* mskw = (const float*)d_in[3];
    const float* mskb = (const float*)d_in[4];
    const float* lblw = (const float*)d_in[5];
    const float* lblb = (const float*)d_in[6];
    float* out = (float*)d_out;

    k_hresize<<<3240, 256>>>(x);
    k_vresize<<<816, 256>>>();
    k_heatpeak<<<256, 256>>>(locw, locb, mskw, mskb, out);
    k_classify<<<256, 256>>>(lblw, lblb, out);
}

// round 12
// speedup vs baseline: 1.2756x; 1.0491x over previous
#include <cuda_runtime.h>
#include <cstdint>

#define FILL_I (-1000000)

#define NPAD_H 18
#define NPAD_M 68

__device__ float g_tmpA[(3 * 2160 + NPAD_H) * 256];
__device__ float g_tmpB[(3 * 2160 + NPAD_M) * 64];
__device__ float g_hx[3 * 256 * 256];
__device__ float g_mx[3 * 64 * 64];
__device__ unsigned g_bits[256 * 8];

#define OFF_COORDS 65536
#define OFF_SURV   66048
#define OFF_LOGITS 66304
#define OFF_LABELS 68096

// compile-time normalized triangle weights (interior outputs, horizontal)
__device__ __forceinline__ constexpr float WAc(int k) {
    return (float)((15.0 - ((k < 15) ? (15 - k) : (k - 15))) / 225.0);
}
__device__ __forceinline__ constexpr float WBc(int k) {
    double d = (k < 60) ? (59.5 - k) : (k - 59.5);
    return (float)((60.0 - d) / 3600.0);
}

// ---------------- K1: horizontal pass, 1 row per block -----------------------
__global__ __launch_bounds__(256) void k_hresize(const float* __restrict__ x) {
    __shared__ float row[4032];         // [0,32) zero | data 32..3871 | zero tail
    __shared__ float pb[4][64];
    int b = blockIdx.x;                 // 6480 = 3ch * 2160 rows
    int c = b / 2160;
    int iy = b - c * 2160;
    const float4* src4 = (const float4*)(x + ((size_t)(c * 2160 + iy)) * 3840);
    for (int j = threadIdx.x; j < 1008; j += 256) {
        float4 v = make_float4(0.f, 0.f, 0.f, 0.f);
        if (j >= 8 && j < 968) v = src4[j - 8];
        *(float4*)(&row[j * 4]) = v;
    }
    __syncthreads();
    int t = threadIdx.x;
    size_t rbase = (size_t)(c * 2160 + iy);

    // A side: output t, taps k=1..29 at row[15t+24+k]
    {
        int sb = 15 * t + 24;
        float a0 = 0.f;
        #pragma unroll
        for (int k = 1; k <= 29; k++)
            a0 = fmaf(WAc(k), row[sb + k], a0);
        if (t == 0 || t == 255) a0 *= (225.f / 197.f);
        g_tmpA[rbase * 256 + t] = a0;
    }

    // B side: output o=t&63, quarter q=t>>6 (warp-uniform)
    {
        int o = t & 63, q = t >> 6;
        int sb = 60 * o + 2;
        float b0 = 0.f;
        #define BQ(K0)                                              \
            _Pragma("unroll")                                       \
            for (int j = 0; j < 30; j++)                            \
                b0 = fmaf(WBc((K0) + j), row[sb + (K0) + j], b0);
        if      (q == 0) { BQ(0)  }
        else if (q == 1) { BQ(30) }
        else if (q == 2) { BQ(60) }
        else             { BQ(90) }
        #undef BQ
        pb[q][o] = b0;
    }
    __syncthreads();
    if (t < 64) {
        float s0 = pb[0][t] + pb[1][t] + pb[2][t] + pb[3][t];
        if (t == 0 || t == 63) s0 *= (8.f / 7.f);
        g_tmpB[rbase * 64 + t] = s0;
    }
}

// ---------------- K2: fused vertical passes (R8 form, 816 blocks) -----------
__global__ __launch_bounds__(256) void k_vresize() {
    int b = blockIdx.x;
    int tid = threadIdx.x;
    if (b < 768) {
        int ch = b >> 8, oy = b & 255;
        float sample = fmaf((float)oy + 0.5f, 8.4375f, -0.5f);
        int s = (int)ceilf(sample - 8.4375f); if (s < 0) s = 0;
        float acc = 0.f, wsum = 0.f;
        #pragma unroll
        for (int k = 0; k < NPAD_H; k++) {
            int pos = s + k;
            float d = fabsf(sample - (float)pos) * (1.0f / 8.4375f);
            float w = fmaxf(1.0f - d, 0.f);
            if (pos > 2159) w = 0.f;
            wsum += w;
            acc = fmaf(w, g_tmpA[((size_t)(ch * 2160 + pos)) * 256 + tid], acc);
        }
        g_hx[(ch * 256 + oy) * 256 + tid] = acc / wsum;
    } else {
        int lin = (b - 768) * 4 + (tid >> 6);
        int ox = tid & 63;
        int ch = lin >> 6, oy = lin & 63;
        float sample = fmaf((float)oy + 0.5f, 33.75f, -0.5f);
        int s = (int)ceilf(sample - 33.75f); if (s < 0) s = 0;
        float acc = 0.f, wsum = 0.f;
        #pragma unroll
        for (int k = 0; k < NPAD_M; k++) {
            int pos = s + k;
            float d = fabsf(sample - (float)pos) * (1.0f / 33.75f);
            float w = fmaxf(1.0f - d, 0.f);
            if (pos > 2159) w = 0.f;
            wsum += w;
            acc = fmaf(w, g_tmpB[((size_t)(ch * 2160 + pos)) * 64 + ox], acc);
        }
        g_mx[(ch * 64 + oy) * 64 + ox] = acc / wsum;
    }
}

// ---------------- K3: heat conv + mask + peak, HALF row per block ------------
// 512 blocks x 128 threads. Block (r, half) computes output cols [h0, h0+128).
// Edge threads additionally compute halo heat cols h0-1 / h0+128.
__global__ __launch_bounds__(128) void k_heatpeak(const float* __restrict__ lw, const float* __restrict__ lb,
                                                  const float* __restrict__ mw, const float* __restrict__ mb,
                                                  float* __restrict__ out) {
    __shared__ float sx[3][5][136];   // cols [h0-4, h0+132), zero OOB
    __shared__ float smx[3][4][36];   // mask input cols [mc0-2, mc0+34)
    __shared__ float sm[2][34];       // mask rows base,base+1; cols [mc0-1, mc0+33)
    __shared__ float sh[3][130];      // heat cols [h0-1, h0+129)
    int tid = threadIdx.x;
    int bidx = blockIdx.x;
    int r = bidx >> 1, half = bidx & 1;
    int h0 = half << 7;
    int base = (r - 1) >> 2;
    int mc0 = h0 >> 2;

    // stage sx: 15 (ch,i) rows x 34 float4
    for (int idx = tid; idx < 510; idx += 128) {
        int c4 = idx % 34;
        int rowi = idx / 34;
        int i = rowi % 5, ch = rowi / 5;
        int gr = r - 2 + i;
        int gc = h0 - 4 + c4 * 4;
        float4 v = make_float4(0.f, 0.f, 0.f, 0.f);
        if (gr >= 0 && gr < 256 && gc >= 0 && gc <= 252)
            v = *(const float4*)(g_hx + (ch << 16) + gr * 256 + gc);
        *(float4*)(&sx[ch][i][c4 * 4]) = v;
    }
    // stage smx (scalar, 432 values)
    for (int idx = tid; idx < 432; idx += 128) {
        int cc = idx % 36;
        int rowi = idx / 36;
        int i = rowi % 4, ch = rowi / 4;
        int gr = base - 1 + i;
        int gc = mc0 - 2 + cc;
        float v = 0.f;
        if (gr >= 0 && gr < 64 && gc >= 0 && gc < 64)
            v = g_mx[(ch * 64 + gr) * 64 + gc];
        smx[ch][i][cc] = v;
    }

    float w[27];
    #pragma unroll
    for (int k = 0; k < 27; k++) w[k] = __ldg(lw + k);
    float bias = __ldg(lb);
    float mbias = __ldg(mb);
    float mwr[27];
    #pragma unroll
    for (int k = 0; k < 27; k++) mwr[k] = __ldg(mw + k);
    __syncthreads();

    // mask conv: 2 rows x 34 cols = 68 values
    if (tid < 68) {
        int rowq = tid / 34, ci = tid % 34;
        float macc = mbias;
        #pragma unroll
        for (int ic = 0; ic < 3; ic++)
            #pragma unroll
            for (int kr = 0; kr < 3; kr++)
                #pragma unroll
                for (int kc = 0; kc < 3; kc++)
                    macc = fmaf(smx[ic][rowq + kr][ci + kc], mwr[ic * 9 + kr * 3 + kc], macc);
        float v = fminf(fmaxf(macc, 0.f), 1.f);
        if (v < 0.6f) v = 0.f;
        sm[rowq][ci] = v;
    }
    __syncthreads();

    // heat for local col(s): lc = tid+1 always; lc=0 for tid 0; lc=129 for tid 127
    int nlc = 1 + (tid == 0) + (tid == 127);
    int lc0 = (tid == 0) ? 0 : (tid + 1);
    for (int e = 0; e < nlc; e++) {
        int lc = (tid == 0) ? (lc0 + e) : ((tid == 127 && e == 1) ? 129 : lc0);
        int j0 = lc + 3;
        float acc[3] = {bias, bias, bias};
        #pragma unroll
        for (int ch = 0; ch < 3; ch++) {
            #pragma unroll
            for (int i = 0; i < 5; i++) {
                float vm = sx[ch][i][j0 - 1];
                float v0 = sx[ch][i][j0];
                float vp = sx[ch][i][j0 + 1];
                #pragma unroll
                for (int j = 0; j < 3; j++) {
                    int kr = i - j;
                    if (kr >= 0 && kr <= 2) {
                        acc[j] = fmaf(w[ch * 9 + kr * 3 + 0], vm,
                                 fmaf(w[ch * 9 + kr * 3 + 1], v0,
                                 fmaf(w[ch * 9 + kr * 3 + 2], vp, acc[j])));
                    }
                }
            }
        }
        int g = h0 - 1 + lc;
        #pragma unroll
        for (int j = 0; j < 3; j++) {
            int rj = r - 1 + j;
            float heat = 0.f;
            if (rj >= 0 && rj < 256 && g >= 0 && g < 256) {
                float hm = fminf(fmaxf(acc[j], 0.f), 1.f);
                if (hm < 0.4f) hm = 0.f;
                int mi = (g >> 2) - mc0 + 1;
                heat = hm * sm[(rj >> 2) - base][mi];
            }
            sh[j][lc] = heat;
        }
    }
    __syncthreads();

    float v = sh[1][tid + 1];
    bool pk = (v > sh[1][tid]) && (v > sh[1][tid + 2]) &&
              (v > sh[0][tid + 1]) && (v > sh[2][tid + 1]);
    unsigned m = __ballot_sync(0xffffffffu, pk);
    if ((tid & 31) == 0) g_bits[r * 8 + half * 4 + (tid >> 5)] = m;
    out[r * 256 + h0 + tid] = v;
}

// ---------------- K4: in-block compact + survive + classify ------------------
__global__ __launch_bounds__(256) void k_classify(const float* __restrict__ W, const float* __restrict__ bias,
                                                  float* __restrict__ out) {
    __shared__ int wsum[8];
    __shared__ int sr[256], scc[256];
    int t = threadIdx.x, bx = blockIdx.x;
    int lane = t & 31, wid = t >> 5;

    uint4 v0 = *(const uint4*)(g_bits + t * 8);
    uint4 v1 = *(const uint4*)(g_bits + t * 8 + 4);
    unsigned bb[8] = {v0.x, v0.y, v0.z, v0.w, v1.x, v1.y, v1.z, v1.w};
    int cnt = 0;
    #pragma unroll
    for (int w = 0; w < 8; w++) cnt += __popc(bb[w]);
    int scan = cnt;
    #pragma unroll
    for (int off = 1; off < 32; off <<= 1) {
        int vv = __shfl_up_sync(0xffffffffu, scan, off);
        if (lane >= off) scan += vv;
    }
    if (lane == 31) wsum[wid] = scan;
    __syncthreads();
    int wbase = 0, total = 0;
    #pragma unroll
    for (int wi = 0; wi < 8; wi++) {
        int s = wsum[wi];
        wbase += (wi < wid) ? s : 0;
        total += s;
    }
    int pos = wbase + scan - cnt;
    #pragma unroll
    for (int w = 0; w < 8; w++) {
        unsigned bits = bb[w];
        while (bits) {
            int j = __ffs(bits) - 1; bits &= bits - 1;
            if (pos < 256) { sr[pos] = t; scc[pos] = w * 32 + j; }
            pos++;
        }
    }
    if (t >= total) { sr[t] = FILL_I; scc[t] = FILL_I; }
    __syncthreads();

    int rme = sr[bx], cme = scc[bx];
    int rt = sr[t], ct = scc[t];
    float dx = (float)rt - (float)rme, dy = (float)ct - (float)cme;
    float d2 = dx * dx + dy * dy;
    int vit = (rt > FILL_I);
    int rej = __syncthreads_or(vit && (d2 > 1.0f) && (d2 < 9.0f));
    int sv = (rme > FILL_I) && !rej;

    if (bx == 0) {
        out[OFF_COORDS + 2 * t]     = (float)rt;
        out[OFF_COORDS + 2 * t + 1] = (float)ct;
    }
    if (t == 0) out[OFF_SURV + bx] = (float)sv;

    if (!sv) {
        if (t < 7) out[OFF_LOGITS + bx * 7 + t] = 0.f;
        if (t == 0) out[OFF_LABELS + bx] = 0.f;
        return;
    }
    int r0 = min(max(rme, 0), 255);
    int c0 = min(max(cme, 0), 255);
    float part[7] = {0.f, 0.f, 0.f, 0.f, 0.f, 0.f, 0.f};
    #pragma unroll
    for (int it = 0; it < 12; it++) {
        int f = t + it * 256;
        int ch = f >> 10, rem = f & 1023, wr = rem >> 5, wc = rem & 31;
        int rr = r0 + wr - 16, cc = c0 + wc - 16;
        float v = 0.f;
        if (rr >= 0 && rr < 256 && cc >= 0 && cc < 256)
            v = g_hx[(ch << 16) + rr * 256 + cc];
        const float* wrow = W + f * 7;
        #pragma unroll
        for (int k = 0; k < 7; k++) part[k] = fmaf(v, wrow[k], part[k]);
    }
    #pragma unroll
    for (int off = 16; off > 0; off >>= 1)
        #pragma unroll
        for (int k = 0; k < 7; k++)
            part[k] += __shfl_down_sync(0xffffffffu, part[k], off);
    __shared__ float sw[8][7];
    if ((t & 31) == 0)
        #pragma unroll
        for (int k = 0; k < 7; k++) sw[t >> 5][k] = part[k];
    __syncthreads();
    if (t == 0) {
        float l[7], e[7];
        float m = -1e30f;
        #pragma unroll
        for (int k = 0; k < 7; k++) {
            float s = bias[k];
            #pragma unroll
            for (int wi = 0; wi < 8; wi++) s += sw[wi][k];
            l[k] = s; m = fmaxf(m, s);
        }
        float s = 0.f;
        #pragma unroll
        for (int k = 0; k < 7; k++) { e[k] = expf(l[k] - m); s += e[k]; }
        float inv = 1.0f / s;
        int best = 0; float bv = -1e30f;
        #pragma unroll
        for (int k = 0; k < 7; k++) {
            float smv = e[k] * inv;
            out[OFF_LOGITS + bx * 7 + k] = smv;
            if (smv > bv) { bv = smv; best = k; }
        }
        out[OFF_LABELS + bx] = (float)best;
    }
}

// ---------------- launch ------------------------------------------------------
extern "C" void kernel_launch(void* const* d_in, const int* in_sizes, int n_in,
                              void* d_out, int out_size) {
    const float* x    = (const float*)d_in[0];
    const float* locw = (const float*)d_in[1];
    const float* locb = (const float*)d_in[2];
    const float* mskw = (const float*)d_in[3];
    const float* mskb = (const float*)d_in[4];
    const float* lblw = (const float*)d_in[5];
    const float* lblb = (const float*)d_in[6];
    float* out = (float*)d_out;

    k_hresize<<<6480, 256>>>(x);
    k_vresize<<<816, 256>>>();
    k_heatpeak<<<512, 128>>>(locw, locb, mskw, mskb, out);
    k_classify<<<256, 256>>>(lblw, lblb, out);
}

// round 13
// speedup vs baseline: 1.3326x; 1.0446x over previous
#include <cuda_runtime.h>
#include <cstdint>

#define FILL_I (-1000000)

#define NPAD_H 18
#define NPAD_M 68

#define PDL_WAIT()    asm volatile("griddepcontrol.wait;" ::: "memory")
#define PDL_TRIGGER() asm volatile("griddepcontrol.launch_dependents;" ::: "memory")

__device__ float g_tmpA[(3 * 2160 + NPAD_H) * 256];
__device__ float g_tmpB[(3 * 2160 + NPAD_M) * 64];
__device__ float g_hx[3 * 256 * 256];
__device__ float g_mx[3 * 64 * 64];
__device__ unsigned g_bits[256 * 8];

#define OFF_COORDS 65536
#define OFF_SURV   66048
#define OFF_LOGITS 66304
#define OFF_LABELS 68096

// compile-time normalized triangle weights (interior outputs, horizontal)
__device__ __forceinline__ constexpr float WAc(int k) {
    return (float)((15.0 - ((k < 15) ? (15 - k) : (k - 15))) / 225.0);
}
__device__ __forceinline__ constexpr float WBc(int k) {
    double d = (k < 60) ? (59.5 - k) : (k - 59.5);
    return (float)((60.0 - d) / 3600.0);
}

// ---------------- K1: horizontal pass, 1 row per block -----------------------
__global__ __launch_bounds__(256) void k_hresize(const float* __restrict__ x) {
    __shared__ float row[4032];
    __shared__ float pb[4][64];
    int b = blockIdx.x;                 // 6480 = 3ch * 2160 rows
    int c = b / 2160;
    int iy = b - c * 2160;
    const float4* src4 = (const float4*)(x + ((size_t)(c * 2160 + iy)) * 3840);
    for (int j = threadIdx.x; j < 1008; j += 256) {
        float4 v = make_float4(0.f, 0.f, 0.f, 0.f);
        if (j >= 8 && j < 968) v = src4[j - 8];
        *(float4*)(&row[j * 4]) = v;
    }
    __syncthreads();
    int t = threadIdx.x;
    size_t rbase = (size_t)(c * 2160 + iy);

    // A side
    {
        int sb = 15 * t + 24;
        float a0 = 0.f;
        #pragma unroll
        for (int k = 1; k <= 29; k++)
            a0 = fmaf(WAc(k), row[sb + k], a0);
        if (t == 0 || t == 255) a0 *= (225.f / 197.f);
        g_tmpA[rbase * 256 + t] = a0;
    }

    // B side
    {
        int o = t & 63, q = t >> 6;
        int sb = 60 * o + 2;
        float b0 = 0.f;
        #define BQ(K0)                                              \
            _Pragma("unroll")                                       \
            for (int j = 0; j < 30; j++)                            \
                b0 = fmaf(WBc((K0) + j), row[sb + (K0) + j], b0);
        if      (q == 0) { BQ(0)  }
        else if (q == 1) { BQ(30) }
        else if (q == 2) { BQ(60) }
        else             { BQ(90) }
        #undef BQ
        pb[q][o] = b0;
    }
    __syncthreads();
    if (t < 64) {
        float s0 = pb[0][t] + pb[1][t] + pb[2][t] + pb[3][t];
        if (t == 0 || t == 63) s0 *= (8.f / 7.f);
        g_tmpB[rbase * 64 + t] = s0;
    }
    PDL_TRIGGER();
}

// ---------------- K2: fused vertical passes (816 blocks) --------------------
__global__ __launch_bounds__(256) void k_vresize() {
    PDL_WAIT();
    int b = blockIdx.x;
    int tid = threadIdx.x;
    if (b < 768) {
        int ch = b >> 8, oy = b & 255;
        float sample = fmaf((float)oy + 0.5f, 8.4375f, -0.5f);
        int s = (int)ceilf(sample - 8.4375f); if (s < 0) s = 0;
        float acc = 0.f, wsum = 0.f;
        #pragma unroll
        for (int k = 0; k < NPAD_H; k++) {
            int pos = s + k;
            float d = fabsf(sample - (float)pos) * (1.0f / 8.4375f);
            float w = fmaxf(1.0f - d, 0.f);
            if (pos > 2159) w = 0.f;
            wsum += w;
            acc = fmaf(w, g_tmpA[((size_t)(ch * 2160 + pos)) * 256 + tid], acc);
        }
        g_hx[(ch * 256 + oy) * 256 + tid] = acc / wsum;
    } else {
        int lin = (b - 768) * 4 + (tid >> 6);
        int ox = tid & 63;
        int ch = lin >> 6, oy = lin & 63;
        float sample = fmaf((float)oy + 0.5f, 33.75f, -0.5f);
        int s = (int)ceilf(sample - 33.75f); if (s < 0) s = 0;
        float acc = 0.f, wsum = 0.f;
        #pragma unroll
        for (int k = 0; k < NPAD_M; k++) {
            int pos = s + k;
            float d = fabsf(sample - (float)pos) * (1.0f / 33.75f);
            float w = fmaxf(1.0f - d, 0.f);
            if (pos > 2159) w = 0.f;
            wsum += w;
            acc = fmaf(w, g_tmpB[((size_t)(ch * 2160 + pos)) * 64 + ox], acc);
        }
        g_mx[(ch * 64 + oy) * 64 + ox] = acc / wsum;
    }
    PDL_TRIGGER();
}

// ---------------- K3: heat conv + mask + peak, half row per block ------------
__global__ __launch_bounds__(128) void k_heatpeak(const float* __restrict__ lw, const float* __restrict__ lb,
                                                  const float* __restrict__ mw, const float* __restrict__ mb,
                                                  float* __restrict__ out) {
    __shared__ float sx[3][5][136];
    __shared__ float smx[3][4][36];
    __shared__ float sm[2][34];
    __shared__ float sh[3][130];
    int tid = threadIdx.x;
    int bidx = blockIdx.x;
    int r = bidx >> 1, half = bidx & 1;
    int h0 = half << 7;
    int base = (r - 1) >> 2;
    int mc0 = h0 >> 2;

    // weights are harness inputs (not producer data) — load before wait
    float w[27];
    #pragma unroll
    for (int k = 0; k < 27; k++) w[k] = __ldg(lw + k);
    float bias = __ldg(lb);
    float mbias = __ldg(mb);
    float mwr[27];
    #pragma unroll
    for (int k = 0; k < 27; k++) mwr[k] = __ldg(mw + k);

    PDL_WAIT();

    for (int idx = tid; idx < 510; idx += 128) {
        int c4 = idx % 34;
        int rowi = idx / 34;
        int i = rowi % 5, ch = rowi / 5;
        int gr = r - 2 + i;
        int gc = h0 - 4 + c4 * 4;
        float4 v = make_float4(0.f, 0.f, 0.f, 0.f);
        if (gr >= 0 && gr < 256 && gc >= 0 && gc <= 252)
            v = *(const float4*)(g_hx + (ch << 16) + gr * 256 + gc);
        *(float4*)(&sx[ch][i][c4 * 4]) = v;
    }
    for (int idx = tid; idx < 432; idx += 128) {
        int cc = idx % 36;
        int rowi = idx / 36;
        int i = rowi % 4, ch = rowi / 4;
        int gr = base - 1 + i;
        int gc = mc0 - 2 + cc;
        float v = 0.f;
        if (gr >= 0 && gr < 64 && gc >= 0 && gc < 64)
            v = g_mx[(ch * 64 + gr) * 64 + gc];
        smx[ch][i][cc] = v;
    }
    __syncthreads();

    if (tid < 68) {
        int rowq = tid / 34, ci = tid % 34;
        float macc = mbias;
        #pragma unroll
        for (int ic = 0; ic < 3; ic++)
            #pragma unroll
            for (int kr = 0; kr < 3; kr++)
                #pragma unroll
                for (int kc = 0; kc < 3; kc++)
                    macc = fmaf(smx[ic][rowq + kr][ci + kc], mwr[ic * 9 + kr * 3 + kc], macc);
        float v = fminf(fmaxf(macc, 0.f), 1.f);
        if (v < 0.6f) v = 0.f;
        sm[rowq][ci] = v;
    }
    __syncthreads();

    int nlc = 1 + (tid == 0) + (tid == 127);
    int lc0 = (tid == 0) ? 0 : (tid + 1);
    for (int e = 0; e < nlc; e++) {
        int lc = (tid == 0) ? (lc0 + e) : ((tid == 127 && e == 1) ? 129 : lc0);
        int j0 = lc + 3;
        float acc[3] = {bias, bias, bias};
        #pragma unroll
        for (int ch = 0; ch < 3; ch++) {
            #pragma unroll
            for (int i = 0; i < 5; i++) {
                float vm = sx[ch][i][j0 - 1];
                float v0 = sx[ch][i][j0];
                float vp = sx[ch][i][j0 + 1];
                #pragma unroll
                for (int j = 0; j < 3; j++) {
                    int kr = i - j;
                    if (kr >= 0 && kr <= 2) {
                        acc[j] = fmaf(w[ch * 9 + kr * 3 + 0], vm,
                                 fmaf(w[ch * 9 + kr * 3 + 1], v0,
                                 fmaf(w[ch * 9 + kr * 3 + 2], vp, acc[j])));
                    }
                }
            }
        }
        int g = h0 - 1 + lc;
        #pragma unroll
        for (int j = 0; j < 3; j++) {
            int rj = r - 1 + j;
            float heat = 0.f;
            if (rj >= 0 && rj < 256 && g >= 0 && g < 256) {
                float hm = fminf(fmaxf(acc[j], 0.f), 1.f);
                if (hm < 0.4f) hm = 0.f;
                int mi = (g >> 2) - mc0 + 1;
                heat = hm * sm[(rj >> 2) - base][mi];
            }
            sh[j][lc] = heat;
        }
    }
    __syncthreads();

    float v = sh[1][tid + 1];
    bool pk = (v > sh[1][tid]) && (v > sh[1][tid + 2]) &&
              (v > sh[0][tid + 1]) && (v > sh[2][tid + 1]);
    unsigned m = __ballot_sync(0xffffffffu, pk);
    if ((tid & 31) == 0) g_bits[r * 8 + half * 4 + (tid >> 5)] = m;
    out[r * 256 + h0 + tid] = v;
    PDL_TRIGGER();
}

// ---------------- K4: compact + survive + classify, 2 candidates/block ------
__global__ __launch_bounds__(256) void k_classify(const float* __restrict__ W, const float* __restrict__ bias,
                                                  float* __restrict__ out) {
    __shared__ int wsum[8];
    __shared__ int sr[256], scc[256];
    int t = threadIdx.x, bx = blockIdx.x;   // bx in [0,128): candidates bx, bx+128
    int lane = t & 31, wid = t >> 5;

    PDL_WAIT();

    uint4 v0 = *(const uint4*)(g_bits + t * 8);
    uint4 v1 = *(const uint4*)(g_bits + t * 8 + 4);
    unsigned bb[8] = {v0.x, v0.y, v0.z, v0.w, v1.x, v1.y, v1.z, v1.w};
    int cnt = 0;
    #pragma unroll
    for (int w = 0; w < 8; w++) cnt += __popc(bb[w]);
    int scan = cnt;
    #pragma unroll
    for (int off = 1; off < 32; off <<= 1) {
        int vv = __shfl_up_sync(0xffffffffu, scan, off);
        if (lane >= off) scan += vv;
    }
    if (lane == 31) wsum[wid] = scan;
    __syncthreads();
    int wbase = 0, total = 0;
    #pragma unroll
    for (int wi = 0; wi < 8; wi++) {
        int s = wsum[wi];
        wbase += (wi < wid) ? s : 0;
        total += s;
    }
    int pos = wbase + scan - cnt;
    #pragma unroll
    for (int w = 0; w < 8; w++) {
        unsigned bits = bb[w];
        while (bits) {
            int j = __ffs(bits) - 1; bits &= bits - 1;
            if (pos < 256) { sr[pos] = t; scc[pos] = w * 32 + j; }
            pos++;
        }
    }
    if (t >= total) { sr[t] = FILL_I; scc[t] = FILL_I; }
    __syncthreads();

    int c0i = bx, c1i = bx + 128;
    int rme0 = sr[c0i], cme0 = scc[c0i];
    int rme1 = sr[c1i], cme1 = scc[c1i];
    int rt = sr[t], ct = scc[t];
    int vit = (rt > FILL_I);
    float dx0 = (float)rt - (float)rme0, dy0 = (float)ct - (float)cme0;
    float d20 = dx0 * dx0 + dy0 * dy0;
    float dx1 = (float)rt - (float)rme1, dy1 = (float)ct - (float)cme1;
    float d21 = dx1 * dx1 + dy1 * dy1;
    int flags = 0;
    if (vit && (d20 > 1.0f) && (d20 < 9.0f)) flags |= 1;
    if (vit && (d21 > 1.0f) && (d21 < 9.0f)) flags |= 2;
    int rej = __syncthreads_or(flags);
    int sv0 = (rme0 > FILL_I) && !(rej & 1);
    int sv1 = (rme1 > FILL_I) && !(rej & 2);

    if (bx == 0) {
        out[OFF_COORDS + 2 * t]     = (float)rt;
        out[OFF_COORDS + 2 * t + 1] = (float)ct;
    }
    if (t == 0) {
        out[OFF_SURV + c0i] = (float)sv0;
        out[OFF_SURV + c1i] = (float)sv1;
    }
    if (!sv0) {
        if (t < 7) out[OFF_LOGITS + c0i * 7 + t] = 0.f;
        if (t == 0) out[OFF_LABELS + c0i] = 0.f;
    }
    if (!sv1) {
        if (t < 7) out[OFF_LOGITS + c1i * 7 + t] = 0.f;
        if (t == 0) out[OFF_LABELS + c1i] = 0.f;
    }
    if (!sv0 && !sv1) return;

    int r0a = min(max(rme0, 0), 255), c0a = min(max(cme0, 0), 255);
    int r0b = min(max(rme1, 0), 255), c0b = min(max(cme1, 0), 255);
    float pa[7] = {0.f, 0.f, 0.f, 0.f, 0.f, 0.f, 0.f};
    float pbv[7] = {0.f, 0.f, 0.f, 0.f, 0.f, 0.f, 0.f};
    #pragma unroll
    for (int it = 0; it < 12; it++) {
        int f = t + it * 256;
        int ch = f >> 10, rem = f & 1023, wr = rem >> 5, wc = rem & 31;
        float va = 0.f, vb = 0.f;
        if (sv0) {
            int rr = r0a + wr - 16, cc = c0a + wc - 16;
            if (rr >= 0 && rr < 256 && cc >= 0 && cc < 256)
                va = g_hx[(ch << 16) + rr * 256 + cc];
        }
        if (sv1) {
            int rr = r0b + wr - 16, cc = c0b + wc - 16;
            if (rr >= 0 && rr < 256 && cc >= 0 && cc < 256)
                vb = g_hx[(ch << 16) + rr * 256 + cc];
        }
        const float* wrow = W + f * 7;
        #pragma unroll
        for (int k = 0; k < 7; k++) {
            float ww = wrow[k];
            pa[k]  = fmaf(va, ww, pa[k]);
            pbv[k] = fmaf(vb, ww, pbv[k]);
        }
    }
    #pragma unroll
    for (int off = 16; off > 0; off >>= 1)
        #pragma unroll
        for (int k = 0; k < 7; k++) {
            pa[k]  += __shfl_down_sync(0xffffffffu, pa[k], off);
            pbv[k] += __shfl_down_sync(0xffffffffu, pbv[k], off);
        }
    __shared__ float swred[8][14];
    if ((t & 31) == 0)
        #pragma unroll
        for (int k = 0; k < 7; k++) {
            swred[t >> 5][k]     = pa[k];
            swred[t >> 5][k + 7] = pbv[k];
        }
    __syncthreads();
    if (t == 0) {
        #pragma unroll
        for (int cand = 0; cand < 2; cand++) {
            int sv = cand ? sv1 : sv0;
            if (!sv) continue;
            int ci = cand ? c1i : c0i;
            float l[7], e[7];
            float m = -1e30f;
            #pragma unroll
            for (int k = 0; k < 7; k++) {
                float s = bias[k];
                #pragma unroll
                for (int wi = 0; wi < 8; wi++) s += swred[wi][k + cand * 7];
                l[k] = s; m = fmaxf(m, s);
            }
            float s = 0.f;
            #pragma unroll
            for (int k = 0; k < 7; k++) { e[k] = expf(l[k] - m); s += e[k]; }
            float inv = 1.0f / s;
            int best = 0; float bv = -1e30f;
            #pragma unroll
            for (int k = 0; k < 7; k++) {
                float smv = e[k] * inv;
                out[OFF_LOGITS + ci * 7 + k] = smv;
                if (smv > bv) { bv = smv; best = k; }
            }
            out[OFF_LABELS + ci] = (float)best;
        }
    }
}

// ---------------- launch ------------------------------------------------------
extern "C" void kernel_launch(void* const* d_in, const int* in_sizes, int n_in,
                              void* d_out, int out_size) {
    const float* x    = (const float*)d_in[0];
    const float* locw = (const float*)d_in[1];
    const float* locb = (const float*)d_in[2];
    const float* mskw = (const float*)d_in[3];
    const float* mskb = (const float*)d_in[4];
    const float* lblw = (const float*)d_in[5];
    const float* lblb = (const float*)d_in[6];
    float* out = (float*)d_out;

    k_hresize<<<6480, 256>>>(x);

    cudaLaunchAttribute attr[1];
    attr[0].id = cudaLaunchAttributeProgrammaticStreamSerialization;
    attr[0].val.programmaticStreamSerializationAllowed = 1;

    {
        cudaLaunchConfig_t cfg = {};
        cfg.gridDim = dim3(816, 1, 1);
        cfg.blockDim = dim3(256, 1, 1);
        cfg.attrs = attr; cfg.numAttrs = 1;
        cudaLaunchKernelEx(&cfg, k_vresize);
    }
    {
        cudaLaunchConfig_t cfg = {};
        cfg.gridDim = dim3(512, 1, 1);
        cfg.blockDim = dim3(128, 1, 1);
        cfg.attrs = attr; cfg.numAttrs = 1;
        cudaLaunchKernelEx(&cfg, k_heatpeak, locw, locb, mskw, mskb, out);
    }
    {
        cudaLaunchConfig_t cfg = {};
        cfg.gridDim = dim3(128, 1, 1);
        cfg.blockDim = dim3(256, 1, 1);
        cfg.attrs = attr; cfg.numAttrs = 1;
        cudaLaunchKernelEx(&cfg, k_classify, lblw, lblb, out);
    }
}